// round 1
// baseline (speedup 1.0000x reference)
#include <cuda_runtime.h>

// Circuit: 20 qubits, all gates are RX on distinct wires applied twice
// (per-batch angle x[b,i], then shared theta[i]). RX gates on different
// wires commute and RX(a)RX(b)=RX(a+b), so from |0..0> the state is the
// product state  ⊗_i RX(x[b,i]+theta[i]) |0>, and
//   <Z_i> = cos^2((x+th)/2) - sin^2((x+th)/2) = cos(x[b,i] + theta[i]).
// Output: [B=32, n_qubits=20] float32.

__global__ void rx_expectation_kernel(const float* __restrict__ x,
                                      const float* __restrict__ thetas,
                                      float* __restrict__ out,
                                      int n_qubits, int total) {
    int idx = blockIdx.x * blockDim.x + threadIdx.x;
    if (idx < total) {
        int w = idx % n_qubits;
        out[idx] = cosf(x[idx] + thetas[w]);
    }
}

extern "C" void kernel_launch(void* const* d_in, const int* in_sizes, int n_in,
                              void* d_out, int out_size) {
    const float* x      = (const float*)d_in[0];   // [B, n_qubits]
    const float* thetas = (const float*)d_in[1];   // [n_qubits]
    float* out = (float*)d_out;                    // [B, n_qubits]

    int n_qubits = in_sizes[1];        // 20
    int total    = out_size;           // B * n_qubits = 640

    int threads = 256;
    int blocks = (total + threads - 1) / threads;
    rx_expectation_kernel<<<blocks, threads>>>(x, thetas, out, n_qubits, total);
}

// round 2
// speedup vs baseline: 1.0839x; 1.0839x over previous
#include <cuda_runtime.h>

// Closed form: out[b,i] = cos(x[b,i] + thetas[i]).  (RX gates on distinct
// wires commute; RX(a)RX(b)=RX(a+b); product state from |0..0>; <Z>=cos(phi).)
// 640 outputs total — the kernel is launch-latency bound, so: one block,
// one thread per element, both loads issued independently to overlap latency.

__global__ void __launch_bounds__(1024, 1)
rx_expectation_kernel(const float* __restrict__ x,
                      const float* __restrict__ thetas,
                      float* __restrict__ out,
                      int n_qubits, int total) {
    int idx = threadIdx.x;
    if (idx < total) {
        int w = idx % n_qubits;
        float t = __ldg(&thetas[w]);   // independent loads -> MLP=2
        float v = __ldg(&x[idx]);
        out[idx] = cosf(v + t);
    }
}

extern "C" void kernel_launch(void* const* d_in, const int* in_sizes, int n_in,
                              void* d_out, int out_size) {
    const float* x      = (const float*)d_in[0];   // [B, n_qubits]
    const float* thetas = (const float*)d_in[1];   // [n_qubits]
    float* out = (float*)d_out;                    // [B, n_qubits]

    int n_qubits = in_sizes[1];        // 20
    int total    = out_size;           // 640

    // total = 640 <= 1024: single block, single launch, no tail.
    rx_expectation_kernel<<<1, total>>>(x, thetas, out, n_qubits, total);
}